// round 1
// baseline (speedup 1.0000x reference)
#include <cuda_runtime.h>
#include <math_constants.h>
#include <cstdint>

#define H 512
#define W 512
#define NB 64              // batch
#define NZ 128             // 64 pred + 64 target images
#define TILE 32
#define ITERS 10

// Ping-pong skeleton buffers: [128][512][512] floats = 134 MB each.
__device__ float g_A[(size_t)NZ * H * W];
__device__ float g_B[(size_t)NZ * H * W];
// Accumulators: [0..63] sum(clp*t) per b, [64..127] sum(clp),
// [128..191] sum(ts*p), [192..255] sum(ts), [256]=sum(p*t), [257]=sum(p), [258]=sum(t)
__device__ float g_acc[259];

// ---------------------------------------------------------------------------
// One soft-skeletonize iteration, fully fused (5x5 effective stencil).
//   min_pool = 3x3 min of x         (x padded with +inf outside image)
//   contour  = relu(3x3 max of min_pool - min_pool)   (min_pool padded -inf)
//   x_new    = relu(x - contour)
// Templated body shared by "first" (reads harness inputs) and "step" kernels.
// ---------------------------------------------------------------------------
__device__ __forceinline__ void skel_body(const float* __restrict__ x,
                                          float* __restrict__ o) {
    __shared__ float sx[36][37];    // x tile with 2-halo
    __shared__ float srm[36][35];   // row-wise 3-min
    __shared__ float smin[34][35];  // 3x3 min pool with 1-halo

    const int ty0 = blockIdx.y * TILE;
    const int tx0 = blockIdx.x * TILE;
    const int tid = threadIdx.y * 32 + threadIdx.x;

    // Load (TILE+4)^2 x values, +inf outside the image (min-pool padding).
    #pragma unroll
    for (int i = tid; i < 36 * 36; i += 256) {
        int r = i / 36, c = i - r * 36;
        int gr = ty0 + r - 2, gc = tx0 + c - 2;
        float v = CUDART_INF_F;
        if (gr >= 0 && gr < H && gc >= 0 && gc < W)
            v = __ldg(&x[(size_t)gr * W + gc]);
        sx[r][c] = v;
    }
    __syncthreads();

    // Row-wise 3-min: srm[r][c] covers x cols c..c+2 (min-pos global col tx0+c-1)
    #pragma unroll
    for (int i = tid; i < 36 * 34; i += 256) {
        int r = i / 34, c = i - r * 34;
        srm[r][c] = fminf(sx[r][c], fminf(sx[r][c + 1], sx[r][c + 2]));
    }
    __syncthreads();

    // Column 3-min -> min_pool. Positions outside the image get -inf
    // (max-pool padding of min_pool).
    #pragma unroll
    for (int i = tid; i < 34 * 34; i += 256) {
        int r = i / 34, c = i - r * 34;
        int gr = ty0 + r - 1, gc = tx0 + c - 1;
        float v = -CUDART_INF_F;
        if (gr >= 0 && gr < H && gc >= 0 && gc < W)
            v = fminf(srm[r][c], fminf(srm[r + 1][c], srm[r + 2][c]));
        smin[r][c] = v;
    }
    __syncthreads();

    // Output: contour + update. Each of 32x8 threads does 4 rows.
    const int c = threadIdx.x;
    #pragma unroll
    for (int rr = threadIdx.y; rr < TILE; rr += 8) {
        float ctr = smin[rr + 1][c + 1];
        float mx = ctr;
        #pragma unroll
        for (int dr = 0; dr < 3; dr++) {
            mx = fmaxf(mx, smin[rr + dr][c]);
            mx = fmaxf(mx, smin[rr + dr][c + 1]);
            mx = fmaxf(mx, smin[rr + dr][c + 2]);
        }
        float contour = fmaxf(mx - ctr, 0.0f);
        float xv = sx[rr + 2][c + 2];
        int gr = ty0 + rr, gc = tx0 + c;
        o[(size_t)gr * W + gc] = fmaxf(xv - contour, 0.0f);
    }
}

__global__ void __launch_bounds__(256)
skel_first(const float* __restrict__ pred, const float* __restrict__ target) {
    int z = blockIdx.z;
    const float* x = (z < NB) ? pred + (size_t)z * H * W
                              : target + (size_t)(z - NB) * H * W;
    float* o = g_A + (size_t)z * H * W;
    skel_body(x, o);
}

__global__ void __launch_bounds__(256)
skel_step(int src) {  // src==0: A->B, src==1: B->A
    int z = blockIdx.z;
    const float* x = (src ? g_B : g_A) + (size_t)z * H * W;
    float*       o = (src ? g_A : g_B) + (size_t)z * H * W;
    skel_body(x, o);
}

// ---------------------------------------------------------------------------
// Reductions: per-batch and global sums. Skeletons live in g_B after 10 iters.
// ---------------------------------------------------------------------------
__global__ void zero_acc() {
    int i = threadIdx.x;
    if (i < 259) g_acc[i] = 0.0f;
}

__global__ void __launch_bounds__(256)
reduce_kernel(const float* __restrict__ pred, const float* __restrict__ target) {
    const int b = blockIdx.y;
    const int N = H * W;
    const float* p   = pred   + (size_t)b * N;
    const float* t   = target + (size_t)b * N;
    const float* clp = g_B + (size_t)b * N;
    const float* ts  = g_B + (size_t)(NB + b) * N;

    float s0 = 0, s1 = 0, s2 = 0, s3 = 0, s4 = 0, s5 = 0, s6 = 0;
    for (int i = blockIdx.x * 256 + threadIdx.x; i < N; i += gridDim.x * 256) {
        float pv = p[i], tv = t[i], cv = clp[i], sv = ts[i];
        s0 += cv * tv;   // cl_pred * target
        s1 += cv;        // cl_pred
        s2 += sv * pv;   // target_skel * pred
        s3 += sv;        // target_skel
        s4 += pv * tv;   // pred * target (dice)
        s5 += pv;
        s6 += tv;
    }
    // warp reduce all 7
    #pragma unroll
    for (int o = 16; o; o >>= 1) {
        s0 += __shfl_down_sync(0xffffffffu, s0, o);
        s1 += __shfl_down_sync(0xffffffffu, s1, o);
        s2 += __shfl_down_sync(0xffffffffu, s2, o);
        s3 += __shfl_down_sync(0xffffffffu, s3, o);
        s4 += __shfl_down_sync(0xffffffffu, s4, o);
        s5 += __shfl_down_sync(0xffffffffu, s5, o);
        s6 += __shfl_down_sync(0xffffffffu, s6, o);
    }
    __shared__ float sh[8][7];
    int lane = threadIdx.x & 31, wid = threadIdx.x >> 5;
    if (lane == 0) {
        sh[wid][0] = s0; sh[wid][1] = s1; sh[wid][2] = s2; sh[wid][3] = s3;
        sh[wid][4] = s4; sh[wid][5] = s5; sh[wid][6] = s6;
    }
    __syncthreads();
    if (threadIdx.x < 7) {
        float v = 0;
        #pragma unroll
        for (int w = 0; w < 8; w++) v += sh[w][threadIdx.x];
        int q = threadIdx.x;
        float* dst = (q < 4) ? &g_acc[q * NB + b] : &g_acc[256 + (q - 4)];
        atomicAdd(dst, v);
    }
}

__global__ void finalize_kernel(float* __restrict__ out) {
    int b = threadIdx.x;  // 64 threads
    float ifl = (g_acc[b] + 1.0f) / (g_acc[64 + b] + 1.0f);
    float tfl = (g_acc[128 + b] + 1.0f) / (g_acc[192 + b] + 1.0f);
    float it = ifl * tfl;
    float s  = ifl + tfl;
    #pragma unroll
    for (int o = 16; o; o >>= 1) {
        it += __shfl_down_sync(0xffffffffu, it, o);
        s  += __shfl_down_sync(0xffffffffu, s,  o);
    }
    __shared__ float sh_it[2], sh_s[2];
    if ((threadIdx.x & 31) == 0) {
        sh_it[threadIdx.x >> 5] = it;
        sh_s[threadIdx.x >> 5]  = s;
    }
    __syncthreads();
    if (threadIdx.x == 0) {
        float IT = sh_it[0] + sh_it[1];
        float S  = sh_s[0] + sh_s[1];
        float I = g_acc[256], Sp = g_acc[257], St = g_acc[258];
        float dice   = 1.0f - (2.0f * I + 1e-6f) / (Sp + St + 1e-6f);
        float cldice = 1.0f - 2.0f * IT / S;
        out[0] = 0.8f * dice + 0.2f * cldice;
    }
}

// ---------------------------------------------------------------------------
extern "C" void kernel_launch(void* const* d_in, const int* in_sizes, int n_in,
                              void* d_out, int out_size) {
    const float* pred   = (const float*)d_in[0];
    const float* target = (const float*)d_in[1];
    float* out = (float*)d_out;

    zero_acc<<<1, 288>>>();

    dim3 blk(32, 8);
    dim3 grd(W / TILE, H / TILE, NZ);   // 16 x 16 x 128

    skel_first<<<grd, blk>>>(pred, target);
    // iters 2..10: even iters read A write B (src=0), odd read B write A (src=1)
    for (int k = 2; k <= ITERS; k++) {
        skel_step<<<grd, blk>>>((k & 1) ? 1 : 0);
    }
    // after iter 10 (even), skeletons are in g_B

    dim3 rgrd(16, NB);
    reduce_kernel<<<rgrd, 256>>>(pred, target);
    finalize_kernel<<<1, 64>>>(out);
}